// round 16
// baseline (speedup 1.0000x reference)
#include <cuda_runtime.h>
#include <cuda_bf16.h>
#include <math.h>
#include <stdint.h>

// Problem constants
#define BB 2
#define NN 1024
#define TT 4096
#define HH 256
#define EE 2
#define DD 2
#define KK 9

// Output layout: responses [B,N,T] | z [B,T,E,D] | mu [B,T,E,D,2] | logvar [B,T,E,D]
#define OFF_R  0
#define OFF_Z  (BB*NN*TT)
#define OFF_MU (OFF_Z + BB*TT*EE*DD)
#define OFF_LV (OFF_MU + BB*TT*EE*DD*2)

// Scratch (device globals)
__device__ __nv_bfloat16 g_w1h[HH*NN], g_w1l[HH*NN];
__device__ __nv_bfloat16 g_w2h[HH*HH], g_w2l[HH*HH];
__device__ __nv_bfloat16 g_h0h[BB*TT*NN], g_h0l[BB*TT*NN];   // conv out [B,T,N] split
__device__ __nv_bfloat16 g_h1h[BB*TT*HH], g_h1l[BB*TT*HH];   // gemm1 out [B,T,H] split
__device__ float g_h2[BB*TT*HH];                              // gemm2 out [B,T,H] f32
__device__ float g_rfp[NN*12];   // 8 scaled rf features + 2 log-weights + pad

// ---------------- helpers ----------------
__device__ __forceinline__ uint32_t smem_u32(const void* p) {
    uint32_t a;
    asm("{ .reg .u64 t; cvta.to.shared.u64 t, %1; cvt.u32.u64 %0, t; }" : "=r"(a) : "l"(p));
    return a;
}
__device__ __forceinline__ void ldsm4(uint32_t* r, uint32_t addr) {
    asm volatile("ldmatrix.sync.aligned.m8n8.x4.shared.b16 {%0,%1,%2,%3}, [%4];"
        : "=r"(r[0]), "=r"(r[1]), "=r"(r[2]), "=r"(r[3]) : "r"(addr));
}
__device__ __forceinline__ void mma_bf16(float* d, const uint32_t* a, const uint32_t* b) {
    asm volatile("mma.sync.aligned.m16n8k16.row.col.f32.bf16.bf16.f32 "
        "{%0,%1,%2,%3}, {%4,%5,%6,%7}, {%8,%9}, {%0,%1,%2,%3};"
        : "+f"(d[0]), "+f"(d[1]), "+f"(d[2]), "+f"(d[3])
        : "r"(a[0]), "r"(a[1]), "r"(a[2]), "r"(a[3]), "r"(b[0]), "r"(b[1]));
}
__device__ __forceinline__ void cp_async16(uint32_t dst, const void* src) {
    asm volatile("cp.async.ca.shared.global [%0], [%1], 16;" :: "r"(dst), "l"(src));
}
__device__ __forceinline__ void cp_commit() {
    asm volatile("cp.async.commit_group;" ::: "memory");
}
template<int N> __device__ __forceinline__ void cp_wait() {
    asm volatile("cp.async.wait_group %0;" :: "n"(N) : "memory");
}

// FMA-only exp (no MUFU)
__device__ __forceinline__ float fast_exp(float x) {
    const float L2E = 1.4426950408889634f;
    float z = fmaf(x, L2E, 12582912.0f);
    float n = z - 12582912.0f;
    float f = fmaf(x, L2E, -n);
    float p = fmaf(f, 1.5403530393e-4f, 1.3333558146e-3f);
    p = fmaf(f, p, 9.6181291076e-3f);
    p = fmaf(f, p, 5.5504108664e-2f);
    p = fmaf(f, p, 2.4022650696e-1f);
    p = fmaf(f, p, 6.9314718056e-1f);
    p = fmaf(f, p, 1.0f);
    float s = __int_as_float((__float_as_int(z) + 127) << 23);
    return p * s;
}

// ---------------------------------------------------------------------------
// Merged prep: w1 split | w2 split | bump prep
// ---------------------------------------------------------------------------
__global__ __launch_bounds__(256) void prep_all_kernel(
    const float* __restrict__ w1, const float* __restrict__ w2,
    const float* __restrict__ rf, const float* __restrict__ ew,
    const float* __restrict__ fs, const float* __restrict__ ltw)
{
    int blk = blockIdx.x;
    if (blk < 1024) {
        int i = blk * 256 + threadIdx.x;
        float v = w1[i];
        __nv_bfloat16 h = __float2bfloat16(v);
        g_w1h[i] = h;
        g_w1l[i] = __float2bfloat16(v - __bfloat162float(h));
    } else if (blk < 1280) {
        int i = (blk - 1024) * 256 + threadIdx.x;
        float v = w2[i];
        __nv_bfloat16 h = __float2bfloat16(v);
        g_w2h[i] = h;
        g_w2l[i] = __float2bfloat16(v - __bfloat162float(h));
    } else {
        int n = (blk - 1280) * 256 + threadIdx.x;
        if (n >= NN) return;
        float tw = expf(ltw[0]);
        float kk = 2.0f / tw;

        float e0 = ew[n*2+0], e1 = ew[n*2+1];
        float m = fmaxf(e0, e1);
        float lse = m + logf(expf(e0 - m) + expf(e1 - m));
        float base = fs[n] - 4.0f / tw - lse;

        float* o = &g_rfp[n*12];
        #pragma unroll
        for (int e = 0; e < EE; e++)
            #pragma unroll
            for (int d = 0; d < DD; d++) {
                float a = rf[(n*EE + e)*DD + d];
                float s, c;
                sincosf(a, &s, &c);
                o[e*4 + d*2 + 0] = kk * s;
                o[e*4 + d*2 + 1] = kk * c;
            }
        o[8] = e0 + base;
        o[9] = e1 + base;
        o[10] = 0.f; o[11] = 0.f;
    }
}

// ---------------------------------------------------------------------------
// bump + readout: responses [B,N,T]
// ---------------------------------------------------------------------------
__global__ __launch_bounds__(128) void bump_kernel(const float* __restrict__ z,
                                                   float* __restrict__ out)
{
    __shared__ float srf[256*12];
    int nbase = blockIdx.z * 256;
    for (int i = threadIdx.x; i < 256*12; i += 128)
        srf[i] = g_rfp[nbase*12 + i];

    int b = blockIdx.y;
    int tb = blockIdx.x * 256 + threadIdx.x;

    float zf0[8], zf1[8];
    #pragma unroll
    for (int u = 0; u < 2; u++) {
        float* zf = u ? zf1 : zf0;
        int t = tb + u * 128;
        #pragma unroll
        for (int e = 0; e < EE; e++)
            #pragma unroll
            for (int d = 0; d < DD; d++) {
                float a = z[(((size_t)b*TT + t)*EE + e)*DD + d];
                float s, c;
                __sincosf(a, &s, &c);
                zf[e*4 + d*2 + 0] = s;
                zf[e*4 + d*2 + 1] = c;
            }
    }
    __syncthreads();

    float* orow = out + OFF_R + ((size_t)b*NN + nbase)*TT + tb;
    #pragma unroll 2
    for (int nn = 0; nn < 256; nn++) {
        const float4 r0 = *(const float4*)&srf[nn*12 + 0];
        const float4 r1 = *(const float4*)&srf[nn*12 + 4];
        const float4 r2 = *(const float4*)&srf[nn*12 + 8];
        float s0a = fmaf(zf0[0], r0.x, fmaf(zf0[1], r0.y, fmaf(zf0[2], r0.z, zf0[3]*r0.w)));
        float s1a = fmaf(zf0[4], r1.x, fmaf(zf0[5], r1.y, fmaf(zf0[6], r1.z, zf0[7]*r1.w)));
        float s0b = fmaf(zf1[0], r0.x, fmaf(zf1[1], r0.y, fmaf(zf1[2], r0.z, zf1[3]*r0.w)));
        float s1b = fmaf(zf1[4], r1.x, fmaf(zf1[5], r1.y, fmaf(zf1[6], r1.z, zf1[7]*r1.w)));
        float ra = fast_exp(s0a + r2.x) + fast_exp(s1a + r2.y);
        float rb = fast_exp(s0b + r2.x) + fast_exp(s1b + r2.y);
        orow[(size_t)nn*TT]       = ra;
        orow[(size_t)nn*TT + 128] = rb;
    }
}

// ---------------------------------------------------------------------------
// depthwise conv, K=9, SAME; output [B,T,N] as bf16 hi/lo  (R9 version)
// ---------------------------------------------------------------------------
__global__ __launch_bounds__(256) void dwconv_t_kernel(const float* __restrict__ x,
                                                       const float* __restrict__ w,
                                                       const float* __restrict__ bias)
{
    __shared__ float xs[32*137];
    __shared__ float sw[32*9];
    __shared__ float sb[32];
    int t0 = blockIdx.x * 128;
    int n0 = blockIdx.y * 32;
    int b  = blockIdx.z;
    int tid = threadIdx.x;

    for (int idx = tid; idx < 32*136; idx += 256) {
        int r = idx / 136, c = idx % 136;
        int t = t0 + c - 4;
        float v = 0.f;
        if (t >= 0 && t < TT) v = x[((size_t)b*NN + n0 + r)*TT + t];
        xs[r*137 + c] = v;
    }
    for (int idx = tid; idx < 288; idx += 256) sw[idx] = w[(size_t)n0*9 + idx];
    if (tid < 32) sb[tid] = bias[n0 + tid];
    __syncthreads();

    int n = tid & 31;
    int tl0 = tid >> 5;
    float wk[9];
    #pragma unroll
    for (int k = 0; k < 9; k++) wk[k] = sw[n*9 + k];
    float bb = sb[n];

    #pragma unroll 4
    for (int p = 0; p < 16; p++) {
        int tl = tl0 + p*8;
        float acc = bb;
        #pragma unroll
        for (int k = 0; k < 9; k++) acc = fmaf(wk[k], xs[n*137 + tl + k], acc);
        size_t oi = ((size_t)b*TT + t0 + tl)*NN + n0 + n;
        __nv_bfloat16 h = __float2bfloat16(acc);
        g_h0h[oi] = h;
        g_h0l[oi] = __float2bfloat16(acc - __bfloat162float(h));
    }
}

// ---------------------------------------------------------------------------
// bf16 3-term split GEMM via mma.sync m16n8k16 (R9 core) with smem-staged
// coalesced epilogue: acc -> smem f32 tile (pitch 132) -> bf162/float2 stores.
// CTA tile 128(m) x 128(t), K-chunk 32, 3-stage cp.async pipeline, 512 thr.
// ---------------------------------------------------------------------------
#define TILE_B   10240          // 128*80
#define STAGE_B  (4*TILE_B)     // 40960
#define GSMEM    (3*STAGE_B)    // 122880  (>= 128*132*4 = 67584 for epilogue)

template<int KDIM, bool OUT_SPLIT>
__global__ __launch_bounds__(512, 1) void gemm_mma_kernel(
    const __nv_bfloat16* __restrict__ Wh, const __nv_bfloat16* __restrict__ Wl,
    const __nv_bfloat16* __restrict__ Xh, const __nv_bfloat16* __restrict__ Xl,
    const float* __restrict__ bias,
    __nv_bfloat16* __restrict__ Yh, __nv_bfloat16* __restrict__ Yl,
    float* __restrict__ Yf)
{
    extern __shared__ char smem[];
    const uint32_t smbase = smem_u32(smem);
    const int tid = threadIdx.x;
    const int wid = tid >> 5;
    const int lane = tid & 31;
    const int wm = wid & 3;
    const int wn = wid >> 2;

    const int t0 = blockIdx.x * 128;
    const int m0 = blockIdx.y * 128;
    const int bz = blockIdx.z;
    const size_t xrow0 = ((size_t)bz * TT + t0);

    auto load_chunk = [&](int c, int stage) {
        const int k0 = c * 32;
        const uint32_t sb = smbase + stage * STAGE_B;
        #pragma unroll
        for (int i = 0; i < 4; i++) {
            int idx = i * 512 + tid;
            int which = idx >> 9;
            int r = (idx >> 2) & 127;
            int seg = idx & 3;
            const __nv_bfloat16* src;
            if      (which == 0) src = Wh + (size_t)(m0 + r) * KDIM + k0;
            else if (which == 1) src = Wl + (size_t)(m0 + r) * KDIM + k0;
            else if (which == 2) src = Xh + (xrow0 + r) * KDIM + k0;
            else                 src = Xl + (xrow0 + r) * KDIM + k0;
            cp_async16(sb + which * TILE_B + r * 80 + seg * 16,
                       (const char*)src + seg * 16);
        }
        cp_commit();
    };

    float acc[2][4][4];
    #pragma unroll
    for (int a = 0; a < 2; a++)
        #pragma unroll
        for (int b = 0; b < 4; b++)
            #pragma unroll
            for (int c = 0; c < 4; c++) acc[a][b][c] = 0.f;

    const int NCH = KDIM / 32;
    load_chunk(0, 0);
    load_chunk(1, 1);

    const uint32_t arow = (uint32_t)(((lane >> 3) & 1) * 8 + (lane & 7));
    const uint32_t akh  = (uint32_t)((lane >> 4) * 16);
    const uint32_t brow = (uint32_t)((lane >> 4) * 8 + (lane & 7));
    const uint32_t bkh  = (uint32_t)(((lane >> 3) & 1) * 16);

    for (int c = 0; c < NCH; c++) {
        cp_wait<1>();
        __syncthreads();
        if (c + 2 < NCH) load_chunk(c + 2, (c + 2) % 3);

        const uint32_t sb  = smbase + (c % 3) * STAGE_B;
        const uint32_t sAh = sb;
        const uint32_t sAl = sb + TILE_B;
        const uint32_t sBh = sb + 2*TILE_B;
        const uint32_t sBl = sb + 3*TILE_B;

        #pragma unroll
        for (int g = 0; g < 2; g++) {
            const int gofs = g * 32;
            uint32_t Ah[2][4], Al[2][4], Bh[2][4], Bl[2][4];
            #pragma unroll
            for (int mt = 0; mt < 2; mt++) {
                uint32_t off = (wm*32 + mt*16 + arow) * 80 + gofs + akh;
                ldsm4(Ah[mt], sAh + off);
                ldsm4(Al[mt], sAl + off);
            }
            #pragma unroll
            for (int p = 0; p < 2; p++) {
                uint32_t off = (wn*32 + p*16 + brow) * 80 + gofs + bkh;
                ldsm4(Bh[p], sBh + off);
                ldsm4(Bl[p], sBl + off);
            }
            #pragma unroll
            for (int mt = 0; mt < 2; mt++)
                #pragma unroll
                for (int nt = 0; nt < 4; nt++)
                    mma_bf16(acc[mt][nt], Ah[mt], &Bh[nt >> 1][(nt & 1) * 2]);
            #pragma unroll
            for (int mt = 0; mt < 2; mt++)
                #pragma unroll
                for (int nt = 0; nt < 4; nt++)
                    mma_bf16(acc[mt][nt], Ah[mt], &Bl[nt >> 1][(nt & 1) * 2]);
            #pragma unroll
            for (int mt = 0; mt < 2; mt++)
                #pragma unroll
                for (int nt = 0; nt < 4; nt++)
                    mma_bf16(acc[mt][nt], Al[mt], &Bh[nt >> 1][(nt & 1) * 2]);
        }
        __syncthreads();
    }

    // ---- epilogue: bias+relu -> smem f32 tile [t_local][m_local] pitch 132 ----
    float* cs = (float*)smem;            // stage smem reused (all reads drained)
    const int lr = lane >> 2;
    const int lc = (lane & 3) * 2;
    #pragma unroll
    for (int mt = 0; mt < 2; mt++) {
        const int mAl = wm*32 + mt*16 + lr;
        const float bv0 = __ldg(&bias[m0 + mAl]);
        const float bv8 = __ldg(&bias[m0 + mAl + 8]);
        #pragma unroll
        for (int nt = 0; nt < 4; nt++) {
            const int tgl = wn*32 + nt*8 + lc;
            cs[(tgl    )*132 + mAl    ] = fmaxf(acc[mt][nt][0] + bv0, 0.f);
            cs[(tgl + 1)*132 + mAl    ] = fmaxf(acc[mt][nt][1] + bv0, 0.f);
            cs[(tgl    )*132 + mAl + 8] = fmaxf(acc[mt][nt][2] + bv8, 0.f);
            cs[(tgl + 1)*132 + mAl + 8] = fmaxf(acc[mt][nt][3] + bv8, 0.f);
        }
    }
    __syncthreads();

    // ---- coalesced store phase: 8192 m-pairs, 16 per thread ----
    #pragma unroll
    for (int it = 0; it < 16; it++) {
        int idx = it * 512 + tid;        // 0..8191
        int r = idx >> 6;                // t_local
        int p = idx & 63;                // m-pair
        float2 v = *(float2*)&cs[r*132 + p*2];
        size_t go = ((size_t)bz*TT + t0 + r) * HH + m0 + p*2;
        if (OUT_SPLIT) {
            __nv_bfloat16 h0 = __float2bfloat16(v.x);
            __nv_bfloat16 h1 = __float2bfloat16(v.y);
            __nv_bfloat162 hv; hv.x = h0; hv.y = h1;
            __nv_bfloat162 lv;
            lv.x = __float2bfloat16(v.x - __bfloat162float(h0));
            lv.y = __float2bfloat16(v.y - __bfloat162float(h1));
            *(__nv_bfloat162*)&Yh[go] = hv;
            *(__nv_bfloat162*)&Yl[go] = lv;
        } else {
            *(float2*)&Yf[go] = v;
        }
    }
}

// ---------------------------------------------------------------------------
// heads v3 (R15 winner): 8 threads per (b,t) row, skewed smem weights.
// ---------------------------------------------------------------------------
#define WSKEW 264
__global__ __launch_bounds__(256) void heads_kernel(const float* __restrict__ wm,
                                                    const float* __restrict__ bm,
                                                    const float* __restrict__ wv,
                                                    const float* __restrict__ bv,
                                                    const float* __restrict__ z,
                                                    float* __restrict__ out)
{
    __shared__ float swm[8*WSKEW];
    __shared__ float swv[4*WSKEW];
    for (int i = threadIdx.x; i < 8*HH; i += 256) {
        int o = i >> 8, h = i & (HH-1);
        swm[o*WSKEW + h + (h >> 5)] = wm[i];
    }
    for (int i = threadIdx.x; i < 4*HH; i += 256) {
        int o = i >> 8, h = i & (HH-1);
        swv[o*WSKEW + h + (h >> 5)] = wv[i];
    }
    __syncthreads();

    const int row = blockIdx.x * 32 + (threadIdx.x >> 3);
    const int sub = threadIdx.x & 7;
    const int hsk = sub * 33;

    float am[8] = {0,0,0,0,0,0,0,0};
    float av[4] = {0,0,0,0};
    const float4* hrow = (const float4*)(g_h2 + (size_t)row * HH + sub * 32);

    #pragma unroll
    for (int q = 0; q < 8; q++) {
        float4 hv = hrow[q];
        int j = hsk + q * 4;
        #pragma unroll
        for (int o = 0; o < 8; o++) {
            am[o] = fmaf(swm[o*WSKEW + j + 0], hv.x, am[o]);
            am[o] = fmaf(swm[o*WSKEW + j + 1], hv.y, am[o]);
            am[o] = fmaf(swm[o*WSKEW + j + 2], hv.z, am[o]);
            am[o] = fmaf(swm[o*WSKEW + j + 3], hv.w, am[o]);
        }
        #pragma unroll
        for (int o = 0; o < 4; o++) {
            av[o] = fmaf(swv[o*WSKEW + j + 0], hv.x, av[o]);
            av[o] = fmaf(swv[o*WSKEW + j + 1], hv.y, av[o]);
            av[o] = fmaf(swv[o*WSKEW + j + 2], hv.z, av[o]);
            av[o] = fmaf(swv[o*WSKEW + j + 3], hv.w, av[o]);
        }
    }

    #pragma unroll
    for (int off = 4; off >= 1; off >>= 1) {
        #pragma unroll
        for (int o = 0; o < 8; o++) am[o] += __shfl_xor_sync(0xFFFFFFFFu, am[o], off);
        #pragma unroll
        for (int o = 0; o < 4; o++) av[o] += __shfl_xor_sync(0xFFFFFFFFu, av[o], off);
    }

    if (sub == 0) {
        #pragma unroll
        for (int p = 0; p < 4; p++) {
            float c0 = am[2*p]   + __ldg(&bm[2*p]);
            float c1 = am[2*p+1] + __ldg(&bm[2*p+1]);
            float inv = rsqrtf(c0*c0 + c1*c1);
            out[OFF_MU + ((size_t)row*4 + p)*2 + 0] = c0 * inv;
            out[OFF_MU + ((size_t)row*4 + p)*2 + 1] = c1 * inv;
            out[OFF_LV + (size_t)row*4 + p] = av[p] + __ldg(&bv[p]);
        }
    }

    if (threadIdx.x < 32) {
        int zi = blockIdx.x * 32 + threadIdx.x;
        ((float4*)(out + OFF_Z))[zi] = ((const float4*)z)[zi];
    }
}

// ---------------------------------------------------------------------------
extern "C" void kernel_launch(void* const* d_in, const int* in_sizes, int n_in,
                              void* d_out, int out_size)
{
    const float* x    = (const float*)d_in[0];
    const float* z    = (const float*)d_in[1];
    const float* dw_w = (const float*)d_in[2];
    const float* dw_b = (const float*)d_in[3];
    const float* w1   = (const float*)d_in[4];
    const float* b1   = (const float*)d_in[5];
    const float* w2   = (const float*)d_in[6];
    const float* b2   = (const float*)d_in[7];
    const float* wm   = (const float*)d_in[8];
    const float* bm   = (const float*)d_in[9];
    const float* wv   = (const float*)d_in[10];
    const float* bv   = (const float*)d_in[11];
    const float* rf   = (const float*)d_in[12];
    const float* ew   = (const float*)d_in[13];
    const float* fs   = (const float*)d_in[14];
    const float* ltw  = (const float*)d_in[15];
    float* out = (float*)d_out;

    void *pw1h, *pw1l, *pw2h, *pw2l, *ph0h, *ph0l, *ph1h, *ph1l, *ph2;
    cudaGetSymbolAddress(&pw1h, g_w1h); cudaGetSymbolAddress(&pw1l, g_w1l);
    cudaGetSymbolAddress(&pw2h, g_w2h); cudaGetSymbolAddress(&pw2l, g_w2l);
    cudaGetSymbolAddress(&ph0h, g_h0h); cudaGetSymbolAddress(&ph0l, g_h0l);
    cudaGetSymbolAddress(&ph1h, g_h1h); cudaGetSymbolAddress(&ph1l, g_h1l);
    cudaGetSymbolAddress(&ph2,  g_h2);

    cudaFuncSetAttribute(gemm_mma_kernel<NN, true>,
                         cudaFuncAttributeMaxDynamicSharedMemorySize, GSMEM);
    cudaFuncSetAttribute(gemm_mma_kernel<HH, false>,
                         cudaFuncAttributeMaxDynamicSharedMemorySize, GSMEM);

    // schedule: dwconv first on main; prep+bump on s2; gemm1 waits on prep.
    cudaStream_t s2;
    cudaStreamCreateWithFlags(&s2, cudaStreamNonBlocking);
    cudaEvent_t e_fork, e_prep, e_bump;
    cudaEventCreateWithFlags(&e_fork, cudaEventDisableTiming);
    cudaEventCreateWithFlags(&e_prep, cudaEventDisableTiming);
    cudaEventCreateWithFlags(&e_bump, cudaEventDisableTiming);

    cudaEventRecord(e_fork, 0);
    cudaStreamWaitEvent(s2, e_fork, 0);
    prep_all_kernel<<<1284, 256, 0, s2>>>(w1, w2, rf, ew, fs, ltw);
    cudaEventRecord(e_prep, s2);
    bump_kernel<<<dim3(TT/256, BB, NN/256), 128, 0, s2>>>(z, out);
    cudaEventRecord(e_bump, s2);

    dwconv_t_kernel<<<dim3(TT/128, NN/32, BB), 256>>>(x, dw_w, dw_b);
    cudaStreamWaitEvent(0, e_prep, 0);     // gemm1 needs weight splits
    gemm_mma_kernel<NN, true><<<dim3(TT/128, HH/128, BB), 512, GSMEM>>>(
        (const __nv_bfloat16*)pw1h, (const __nv_bfloat16*)pw1l,
        (const __nv_bfloat16*)ph0h, (const __nv_bfloat16*)ph0l,
        b1, (__nv_bfloat16*)ph1h, (__nv_bfloat16*)ph1l, nullptr);
    gemm_mma_kernel<HH, false><<<dim3(TT/128, HH/128, BB), 512, GSMEM>>>(
        (const __nv_bfloat16*)pw2h, (const __nv_bfloat16*)pw2l,
        (const __nv_bfloat16*)ph1h, (const __nv_bfloat16*)ph1l,
        b2, nullptr, nullptr, (float*)ph2);
    heads_kernel<<<256, 256>>>(wm, bm, wv, bv, z, out);

    cudaStreamWaitEvent(0, e_bump, 0);     // join bump branch before capture ends
}

// round 17
// speedup vs baseline: 1.1631x; 1.1631x over previous
#include <cuda_runtime.h>
#include <cuda_bf16.h>
#include <math.h>
#include <stdint.h>

// Problem constants
#define BB 2
#define NN 1024
#define TT 4096
#define HH 256
#define EE 2
#define DD 2
#define KK 9

// Output layout: responses [B,N,T] | z [B,T,E,D] | mu [B,T,E,D,2] | logvar [B,T,E,D]
#define OFF_R  0
#define OFF_Z  (BB*NN*TT)
#define OFF_MU (OFF_Z + BB*TT*EE*DD)
#define OFF_LV (OFF_MU + BB*TT*EE*DD*2)

// Scratch (device globals)
__device__ __nv_bfloat16 g_w1h[HH*NN], g_w1l[HH*NN];
__device__ __nv_bfloat16 g_w2h[HH*HH], g_w2l[HH*HH];
__device__ __nv_bfloat16 g_h0h[BB*TT*NN], g_h0l[BB*TT*NN];   // conv out [B,T,N] split
__device__ __nv_bfloat16 g_h1h[BB*TT*HH], g_h1l[BB*TT*HH];   // gemm1 out [B,T,H] split
__device__ float g_h2[BB*TT*HH];                              // gemm2 out [B,T,H] f32
__device__ float g_rfp[NN*12];   // 8 scaled rf features + 2 log-weights + pad

// ---------------- helpers ----------------
__device__ __forceinline__ uint32_t smem_u32(const void* p) {
    uint32_t a;
    asm("{ .reg .u64 t; cvta.to.shared.u64 t, %1; cvt.u32.u64 %0, t; }" : "=r"(a) : "l"(p));
    return a;
}
__device__ __forceinline__ void ldsm4(uint32_t* r, uint32_t addr) {
    asm volatile("ldmatrix.sync.aligned.m8n8.x4.shared.b16 {%0,%1,%2,%3}, [%4];"
        : "=r"(r[0]), "=r"(r[1]), "=r"(r[2]), "=r"(r[3]) : "r"(addr));
}
__device__ __forceinline__ void mma_bf16(float* d, const uint32_t* a, const uint32_t* b) {
    asm volatile("mma.sync.aligned.m16n8k16.row.col.f32.bf16.bf16.f32 "
        "{%0,%1,%2,%3}, {%4,%5,%6,%7}, {%8,%9}, {%0,%1,%2,%3};"
        : "+f"(d[0]), "+f"(d[1]), "+f"(d[2]), "+f"(d[3])
        : "r"(a[0]), "r"(a[1]), "r"(a[2]), "r"(a[3]), "r"(b[0]), "r"(b[1]));
}
__device__ __forceinline__ void cp_async16(uint32_t dst, const void* src) {
    asm volatile("cp.async.ca.shared.global [%0], [%1], 16;" :: "r"(dst), "l"(src));
}
__device__ __forceinline__ void cp_commit() {
    asm volatile("cp.async.commit_group;" ::: "memory");
}
template<int N> __device__ __forceinline__ void cp_wait() {
    asm volatile("cp.async.wait_group %0;" :: "n"(N) : "memory");
}

// FMA-only exp (no MUFU)
__device__ __forceinline__ float fast_exp(float x) {
    const float L2E = 1.4426950408889634f;
    float z = fmaf(x, L2E, 12582912.0f);
    float n = z - 12582912.0f;
    float f = fmaf(x, L2E, -n);
    float p = fmaf(f, 1.5403530393e-4f, 1.3333558146e-3f);
    p = fmaf(f, p, 9.6181291076e-3f);
    p = fmaf(f, p, 5.5504108664e-2f);
    p = fmaf(f, p, 2.4022650696e-1f);
    p = fmaf(f, p, 6.9314718056e-1f);
    p = fmaf(f, p, 1.0f);
    float s = __int_as_float((__float_as_int(z) + 127) << 23);
    return p * s;
}

// ---------------------------------------------------------------------------
// Merged prep: w1 split | w2 split | bump prep
// ---------------------------------------------------------------------------
__global__ __launch_bounds__(256) void prep_all_kernel(
    const float* __restrict__ w1, const float* __restrict__ w2,
    const float* __restrict__ rf, const float* __restrict__ ew,
    const float* __restrict__ fs, const float* __restrict__ ltw)
{
    int blk = blockIdx.x;
    if (blk < 1024) {
        int i = blk * 256 + threadIdx.x;
        float v = w1[i];
        __nv_bfloat16 h = __float2bfloat16(v);
        g_w1h[i] = h;
        g_w1l[i] = __float2bfloat16(v - __bfloat162float(h));
    } else if (blk < 1280) {
        int i = (blk - 1024) * 256 + threadIdx.x;
        float v = w2[i];
        __nv_bfloat16 h = __float2bfloat16(v);
        g_w2h[i] = h;
        g_w2l[i] = __float2bfloat16(v - __bfloat162float(h));
    } else {
        int n = (blk - 1280) * 256 + threadIdx.x;
        if (n >= NN) return;
        float tw = expf(ltw[0]);
        float kk = 2.0f / tw;

        float e0 = ew[n*2+0], e1 = ew[n*2+1];
        float m = fmaxf(e0, e1);
        float lse = m + logf(expf(e0 - m) + expf(e1 - m));
        float base = fs[n] - 4.0f / tw - lse;

        float* o = &g_rfp[n*12];
        #pragma unroll
        for (int e = 0; e < EE; e++)
            #pragma unroll
            for (int d = 0; d < DD; d++) {
                float a = rf[(n*EE + e)*DD + d];
                float s, c;
                sincosf(a, &s, &c);
                o[e*4 + d*2 + 0] = kk * s;
                o[e*4 + d*2 + 1] = kk * c;
            }
        o[8] = e0 + base;
        o[9] = e1 + base;
        o[10] = 0.f; o[11] = 0.f;
    }
}

// ---------------------------------------------------------------------------
// bump + readout: responses [B,N,T]
// ---------------------------------------------------------------------------
__global__ __launch_bounds__(128) void bump_kernel(const float* __restrict__ z,
                                                   float* __restrict__ out)
{
    __shared__ float srf[256*12];
    int nbase = blockIdx.z * 256;
    for (int i = threadIdx.x; i < 256*12; i += 128)
        srf[i] = g_rfp[nbase*12 + i];

    int b = blockIdx.y;
    int tb = blockIdx.x * 256 + threadIdx.x;

    float zf0[8], zf1[8];
    #pragma unroll
    for (int u = 0; u < 2; u++) {
        float* zf = u ? zf1 : zf0;
        int t = tb + u * 128;
        #pragma unroll
        for (int e = 0; e < EE; e++)
            #pragma unroll
            for (int d = 0; d < DD; d++) {
                float a = z[(((size_t)b*TT + t)*EE + e)*DD + d];
                float s, c;
                __sincosf(a, &s, &c);
                zf[e*4 + d*2 + 0] = s;
                zf[e*4 + d*2 + 1] = c;
            }
    }
    __syncthreads();

    float* orow = out + OFF_R + ((size_t)b*NN + nbase)*TT + tb;
    #pragma unroll 2
    for (int nn = 0; nn < 256; nn++) {
        const float4 r0 = *(const float4*)&srf[nn*12 + 0];
        const float4 r1 = *(const float4*)&srf[nn*12 + 4];
        const float4 r2 = *(const float4*)&srf[nn*12 + 8];
        float s0a = fmaf(zf0[0], r0.x, fmaf(zf0[1], r0.y, fmaf(zf0[2], r0.z, zf0[3]*r0.w)));
        float s1a = fmaf(zf0[4], r1.x, fmaf(zf0[5], r1.y, fmaf(zf0[6], r1.z, zf0[7]*r1.w)));
        float s0b = fmaf(zf1[0], r0.x, fmaf(zf1[1], r0.y, fmaf(zf1[2], r0.z, zf1[3]*r0.w)));
        float s1b = fmaf(zf1[4], r1.x, fmaf(zf1[5], r1.y, fmaf(zf1[6], r1.z, zf1[7]*r1.w)));
        float ra = fast_exp(s0a + r2.x) + fast_exp(s1a + r2.y);
        float rb = fast_exp(s0b + r2.x) + fast_exp(s1b + r2.y);
        orow[(size_t)nn*TT]       = ra;
        orow[(size_t)nn*TT + 128] = rb;
    }
}

// ---------------------------------------------------------------------------
// depthwise conv, K=9, SAME; output [B,T,N] as bf16 hi/lo  (R9 version)
// ---------------------------------------------------------------------------
__global__ __launch_bounds__(256) void dwconv_t_kernel(const float* __restrict__ x,
                                                       const float* __restrict__ w,
                                                       const float* __restrict__ bias)
{
    __shared__ float xs[32*137];
    __shared__ float sw[32*9];
    __shared__ float sb[32];
    int t0 = blockIdx.x * 128;
    int n0 = blockIdx.y * 32;
    int b  = blockIdx.z;
    int tid = threadIdx.x;

    for (int idx = tid; idx < 32*136; idx += 256) {
        int r = idx / 136, c = idx % 136;
        int t = t0 + c - 4;
        float v = 0.f;
        if (t >= 0 && t < TT) v = x[((size_t)b*NN + n0 + r)*TT + t];
        xs[r*137 + c] = v;
    }
    for (int idx = tid; idx < 288; idx += 256) sw[idx] = w[(size_t)n0*9 + idx];
    if (tid < 32) sb[tid] = bias[n0 + tid];
    __syncthreads();

    int n = tid & 31;
    int tl0 = tid >> 5;
    float wk[9];
    #pragma unroll
    for (int k = 0; k < 9; k++) wk[k] = sw[n*9 + k];
    float bb = sb[n];

    #pragma unroll 4
    for (int p = 0; p < 16; p++) {
        int tl = tl0 + p*8;
        float acc = bb;
        #pragma unroll
        for (int k = 0; k < 9; k++) acc = fmaf(wk[k], xs[n*137 + tl + k], acc);
        size_t oi = ((size_t)b*TT + t0 + tl)*NN + n0 + n;
        __nv_bfloat16 h = __float2bfloat16(acc);
        g_h0h[oi] = h;
        g_h0l[oi] = __float2bfloat16(acc - __bfloat162float(h));
    }
}

// ---------------------------------------------------------------------------
// bf16 3-term split GEMM via mma.sync m16n8k16 with smem-staged coalesced
// epilogue (R16 kernel — measured 47.8us on gemm1).
// CTA tile 128(m) x 128(t), K-chunk 32, 3-stage cp.async pipeline, 512 thr.
// ---------------------------------------------------------------------------
#define TILE_B   10240          // 128*80
#define STAGE_B  (4*TILE_B)     // 40960
#define GSMEM    (3*STAGE_B)    // 122880  (>= 128*132*4 = 67584 for epilogue)

template<int KDIM, bool OUT_SPLIT>
__global__ __launch_bounds__(512, 1) void gemm_mma_kernel(
    const __nv_bfloat16* __restrict__ Wh, const __nv_bfloat16* __restrict__ Wl,
    const __nv_bfloat16* __restrict__ Xh, const __nv_bfloat16* __restrict__ Xl,
    const float* __restrict__ bias,
    __nv_bfloat16* __restrict__ Yh, __nv_bfloat16* __restrict__ Yl,
    float* __restrict__ Yf)
{
    extern __shared__ char smem[];
    const uint32_t smbase = smem_u32(smem);
    const int tid = threadIdx.x;
    const int wid = tid >> 5;
    const int lane = tid & 31;
    const int wm = wid & 3;
    const int wn = wid >> 2;

    const int t0 = blockIdx.x * 128;
    const int m0 = blockIdx.y * 128;
    const int bz = blockIdx.z;
    const size_t xrow0 = ((size_t)bz * TT + t0);

    auto load_chunk = [&](int c, int stage) {
        const int k0 = c * 32;
        const uint32_t sb = smbase + stage * STAGE_B;
        #pragma unroll
        for (int i = 0; i < 4; i++) {
            int idx = i * 512 + tid;
            int which = idx >> 9;
            int r = (idx >> 2) & 127;
            int seg = idx & 3;
            const __nv_bfloat16* src;
            if      (which == 0) src = Wh + (size_t)(m0 + r) * KDIM + k0;
            else if (which == 1) src = Wl + (size_t)(m0 + r) * KDIM + k0;
            else if (which == 2) src = Xh + (xrow0 + r) * KDIM + k0;
            else                 src = Xl + (xrow0 + r) * KDIM + k0;
            cp_async16(sb + which * TILE_B + r * 80 + seg * 16,
                       (const char*)src + seg * 16);
        }
        cp_commit();
    };

    float acc[2][4][4];
    #pragma unroll
    for (int a = 0; a < 2; a++)
        #pragma unroll
        for (int b = 0; b < 4; b++)
            #pragma unroll
            for (int c = 0; c < 4; c++) acc[a][b][c] = 0.f;

    const int NCH = KDIM / 32;
    load_chunk(0, 0);
    load_chunk(1, 1);

    const uint32_t arow = (uint32_t)(((lane >> 3) & 1) * 8 + (lane & 7));
    const uint32_t akh  = (uint32_t)((lane >> 4) * 16);
    const uint32_t brow = (uint32_t)((lane >> 4) * 8 + (lane & 7));
    const uint32_t bkh  = (uint32_t)(((lane >> 3) & 1) * 16);

    for (int c = 0; c < NCH; c++) {
        cp_wait<1>();
        __syncthreads();
        if (c + 2 < NCH) load_chunk(c + 2, (c + 2) % 3);

        const uint32_t sb  = smbase + (c % 3) * STAGE_B;
        const uint32_t sAh = sb;
        const uint32_t sAl = sb + TILE_B;
        const uint32_t sBh = sb + 2*TILE_B;
        const uint32_t sBl = sb + 3*TILE_B;

        #pragma unroll
        for (int g = 0; g < 2; g++) {
            const int gofs = g * 32;
            uint32_t Ah[2][4], Al[2][4], Bh[2][4], Bl[2][4];
            #pragma unroll
            for (int mt = 0; mt < 2; mt++) {
                uint32_t off = (wm*32 + mt*16 + arow) * 80 + gofs + akh;
                ldsm4(Ah[mt], sAh + off);
                ldsm4(Al[mt], sAl + off);
            }
            #pragma unroll
            for (int p = 0; p < 2; p++) {
                uint32_t off = (wn*32 + p*16 + brow) * 80 + gofs + bkh;
                ldsm4(Bh[p], sBh + off);
                ldsm4(Bl[p], sBl + off);
            }
            #pragma unroll
            for (int mt = 0; mt < 2; mt++)
                #pragma unroll
                for (int nt = 0; nt < 4; nt++)
                    mma_bf16(acc[mt][nt], Ah[mt], &Bh[nt >> 1][(nt & 1) * 2]);
            #pragma unroll
            for (int mt = 0; mt < 2; mt++)
                #pragma unroll
                for (int nt = 0; nt < 4; nt++)
                    mma_bf16(acc[mt][nt], Ah[mt], &Bl[nt >> 1][(nt & 1) * 2]);
            #pragma unroll
            for (int mt = 0; mt < 2; mt++)
                #pragma unroll
                for (int nt = 0; nt < 4; nt++)
                    mma_bf16(acc[mt][nt], Al[mt], &Bh[nt >> 1][(nt & 1) * 2]);
        }
        __syncthreads();
    }

    // ---- epilogue: bias+relu -> smem f32 tile [t_local][m_local] pitch 132 ----
    float* cs = (float*)smem;            // stage smem reused (all reads drained)
    const int lr = lane >> 2;
    const int lc = (lane & 3) * 2;
    #pragma unroll
    for (int mt = 0; mt < 2; mt++) {
        const int mAl = wm*32 + mt*16 + lr;
        const float bv0 = __ldg(&bias[m0 + mAl]);
        const float bv8 = __ldg(&bias[m0 + mAl + 8]);
        #pragma unroll
        for (int nt = 0; nt < 4; nt++) {
            const int tgl = wn*32 + nt*8 + lc;
            cs[(tgl    )*132 + mAl    ] = fmaxf(acc[mt][nt][0] + bv0, 0.f);
            cs[(tgl + 1)*132 + mAl    ] = fmaxf(acc[mt][nt][1] + bv0, 0.f);
            cs[(tgl    )*132 + mAl + 8] = fmaxf(acc[mt][nt][2] + bv8, 0.f);
            cs[(tgl + 1)*132 + mAl + 8] = fmaxf(acc[mt][nt][3] + bv8, 0.f);
        }
    }
    __syncthreads();

    // ---- coalesced store phase: 8192 m-pairs, 16 per thread ----
    #pragma unroll
    for (int it = 0; it < 16; it++) {
        int idx = it * 512 + tid;        // 0..8191
        int r = idx >> 6;                // t_local
        int p = idx & 63;                // m-pair
        float2 v = *(float2*)&cs[r*132 + p*2];
        size_t go = ((size_t)bz*TT + t0 + r) * HH + m0 + p*2;
        if (OUT_SPLIT) {
            __nv_bfloat16 h0 = __float2bfloat16(v.x);
            __nv_bfloat16 h1 = __float2bfloat16(v.y);
            __nv_bfloat162 hv; hv.x = h0; hv.y = h1;
            __nv_bfloat162 lv;
            lv.x = __float2bfloat16(v.x - __bfloat162float(h0));
            lv.y = __float2bfloat16(v.y - __bfloat162float(h1));
            *(__nv_bfloat162*)&Yh[go] = hv;
            *(__nv_bfloat162*)&Yl[go] = lv;
        } else {
            *(float2*)&Yf[go] = v;
        }
    }
}

// ---------------------------------------------------------------------------
// heads v3 (R15 winner): 8 threads per (b,t) row, skewed smem weights.
// ---------------------------------------------------------------------------
#define WSKEW 264
__global__ __launch_bounds__(256) void heads_kernel(const float* __restrict__ wm,
                                                    const float* __restrict__ bm,
                                                    const float* __restrict__ wv,
                                                    const float* __restrict__ bv,
                                                    const float* __restrict__ z,
                                                    float* __restrict__ out)
{
    __shared__ float swm[8*WSKEW];
    __shared__ float swv[4*WSKEW];
    for (int i = threadIdx.x; i < 8*HH; i += 256) {
        int o = i >> 8, h = i & (HH-1);
        swm[o*WSKEW + h + (h >> 5)] = wm[i];
    }
    for (int i = threadIdx.x; i < 4*HH; i += 256) {
        int o = i >> 8, h = i & (HH-1);
        swv[o*WSKEW + h + (h >> 5)] = wv[i];
    }
    __syncthreads();

    const int row = blockIdx.x * 32 + (threadIdx.x >> 3);
    const int sub = threadIdx.x & 7;
    const int hsk = sub * 33;

    float am[8] = {0,0,0,0,0,0,0,0};
    float av[4] = {0,0,0,0};
    const float4* hrow = (const float4*)(g_h2 + (size_t)row * HH + sub * 32);

    #pragma unroll
    for (int q = 0; q < 8; q++) {
        float4 hv = hrow[q];
        int j = hsk + q * 4;
        #pragma unroll
        for (int o = 0; o < 8; o++) {
            am[o] = fmaf(swm[o*WSKEW + j + 0], hv.x, am[o]);
            am[o] = fmaf(swm[o*WSKEW + j + 1], hv.y, am[o]);
            am[o] = fmaf(swm[o*WSKEW + j + 2], hv.z, am[o]);
            am[o] = fmaf(swm[o*WSKEW + j + 3], hv.w, am[o]);
        }
        #pragma unroll
        for (int o = 0; o < 4; o++) {
            av[o] = fmaf(swv[o*WSKEW + j + 0], hv.x, av[o]);
            av[o] = fmaf(swv[o*WSKEW + j + 1], hv.y, av[o]);
            av[o] = fmaf(swv[o*WSKEW + j + 2], hv.z, av[o]);
            av[o] = fmaf(swv[o*WSKEW + j + 3], hv.w, av[o]);
        }
    }

    #pragma unroll
    for (int off = 4; off >= 1; off >>= 1) {
        #pragma unroll
        for (int o = 0; o < 8; o++) am[o] += __shfl_xor_sync(0xFFFFFFFFu, am[o], off);
        #pragma unroll
        for (int o = 0; o < 4; o++) av[o] += __shfl_xor_sync(0xFFFFFFFFu, av[o], off);
    }

    if (sub == 0) {
        #pragma unroll
        for (int p = 0; p < 4; p++) {
            float c0 = am[2*p]   + __ldg(&bm[2*p]);
            float c1 = am[2*p+1] + __ldg(&bm[2*p+1]);
            float inv = rsqrtf(c0*c0 + c1*c1);
            out[OFF_MU + ((size_t)row*4 + p)*2 + 0] = c0 * inv;
            out[OFF_MU + ((size_t)row*4 + p)*2 + 1] = c1 * inv;
            out[OFF_LV + (size_t)row*4 + p] = av[p] + __ldg(&bv[p]);
        }
    }

    if (threadIdx.x < 32) {
        int zi = blockIdx.x * 32 + threadIdx.x;
        ((float4*)(out + OFF_Z))[zi] = ((const float4*)z)[zi];
    }
}

// ---------------------------------------------------------------------------
extern "C" void kernel_launch(void* const* d_in, const int* in_sizes, int n_in,
                              void* d_out, int out_size)
{
    const float* x    = (const float*)d_in[0];
    const float* z    = (const float*)d_in[1];
    const float* dw_w = (const float*)d_in[2];
    const float* dw_b = (const float*)d_in[3];
    const float* w1   = (const float*)d_in[4];
    const float* b1   = (const float*)d_in[5];
    const float* w2   = (const float*)d_in[6];
    const float* b2   = (const float*)d_in[7];
    const float* wm   = (const float*)d_in[8];
    const float* bm   = (const float*)d_in[9];
    const float* wv   = (const float*)d_in[10];
    const float* bv   = (const float*)d_in[11];
    const float* rf   = (const float*)d_in[12];
    const float* ew   = (const float*)d_in[13];
    const float* fs   = (const float*)d_in[14];
    const float* ltw  = (const float*)d_in[15];
    float* out = (float*)d_out;

    void *pw1h, *pw1l, *pw2h, *pw2l, *ph0h, *ph0l, *ph1h, *ph1l, *ph2;
    cudaGetSymbolAddress(&pw1h, g_w1h); cudaGetSymbolAddress(&pw1l, g_w1l);
    cudaGetSymbolAddress(&pw2h, g_w2h); cudaGetSymbolAddress(&pw2l, g_w2l);
    cudaGetSymbolAddress(&ph0h, g_h0h); cudaGetSymbolAddress(&ph0l, g_h0l);
    cudaGetSymbolAddress(&ph1h, g_h1h); cudaGetSymbolAddress(&ph1l, g_h1l);
    cudaGetSymbolAddress(&ph2,  g_h2);

    cudaFuncSetAttribute(gemm_mma_kernel<NN, true>,
                         cudaFuncAttributeMaxDynamicSharedMemorySize, GSMEM);
    cudaFuncSetAttribute(gemm_mma_kernel<HH, false>,
                         cudaFuncAttributeMaxDynamicSharedMemorySize, GSMEM);

    // R15 schedule (measured best): prep on main, bump forked onto s2.
    cudaStream_t s2;
    cudaStreamCreateWithFlags(&s2, cudaStreamNonBlocking);
    cudaEvent_t e1, e2;
    cudaEventCreateWithFlags(&e1, cudaEventDisableTiming);
    cudaEventCreateWithFlags(&e2, cudaEventDisableTiming);

    prep_all_kernel<<<1284, 256>>>(w1, w2, rf, ew, fs, ltw);
    cudaEventRecord(e1, 0);
    cudaStreamWaitEvent(s2, e1, 0);
    bump_kernel<<<dim3(TT/256, BB, NN/256), 128, 0, s2>>>(z, out);
    cudaEventRecord(e2, s2);

    // encoder path on main stream
    dwconv_t_kernel<<<dim3(TT/128, NN/32, BB), 256>>>(x, dw_w, dw_b);
    gemm_mma_kernel<NN, true><<<dim3(TT/128, HH/128, BB), 512, GSMEM>>>(
        (const __nv_bfloat16*)pw1h, (const __nv_bfloat16*)pw1l,
        (const __nv_bfloat16*)ph0h, (const __nv_bfloat16*)ph0l,
        b1, (__nv_bfloat16*)ph1h, (__nv_bfloat16*)ph1l, nullptr);
    gemm_mma_kernel<HH, false><<<dim3(TT/128, HH/128, BB), 512, GSMEM>>>(
        (const __nv_bfloat16*)pw2h, (const __nv_bfloat16*)pw2l,
        (const __nv_bfloat16*)ph1h, (const __nv_bfloat16*)ph1l,
        b2, nullptr, nullptr, (float*)ph2);
    heads_kernel<<<256, 256>>>(wm, bm, wv, bv, z, out);

    cudaStreamWaitEvent(0, e2, 0);   // join bump branch before capture ends
}